// round 9
// baseline (speedup 1.0000x reference)
#include <cuda_runtime.h>
#include <cuda_fp16.h>
#include <cstdint>
#include <cstddef>

#define NE 16
#define HD 2048
#define ID 1536
#define TT 32768

// ---------------- device scratch (allocation-free rule) -------------------------
__device__ __half g_xh[(size_t)TT * HD];                  // x fp16          (128MB)
__device__ __half g_hid[(size_t)TT * ID];                 // silu(g)*up fp16 ( 96MB)
__device__ __half g_wh[(size_t)NE * 3 * HD * ID];         // fp16 weights    (302MB)

// ---------------- helpers -------------------------------------------------------
__device__ __forceinline__ uint32_t smem_u32(const void* p) {
    uint32_t a;
    asm("{ .reg .u64 t; cvta.to.shared.u64 t, %1; cvt.u32.u64 %0, t; }" : "=r"(a) : "l"(p));
    return a;
}
__device__ __forceinline__ void cp16(uint32_t dst, const void* src) {
    asm volatile("cp.async.cg.shared.global [%0], [%1], 16;" :: "r"(dst), "l"(src));
}
__device__ __forceinline__ void ldsm4(uint32_t& r0, uint32_t& r1, uint32_t& r2,
                                      uint32_t& r3, uint32_t a) {
    asm volatile("ldmatrix.sync.aligned.m8n8.x4.shared.b16 {%0,%1,%2,%3}, [%4];"
                 : "=r"(r0), "=r"(r1), "=r"(r2), "=r"(r3) : "r"(a));
}
__device__ __forceinline__ void ldsm4t(uint32_t& r0, uint32_t& r1, uint32_t& r2,
                                       uint32_t& r3, uint32_t a) {
    asm volatile("ldmatrix.sync.aligned.m8n8.x4.trans.shared.b16 {%0,%1,%2,%3}, [%4];"
                 : "=r"(r0), "=r"(r1), "=r"(r2), "=r"(r3) : "r"(a));
}
__device__ __forceinline__ void mma16816(float* c, uint32_t a0, uint32_t a1, uint32_t a2,
                                         uint32_t a3, uint32_t b0, uint32_t b1) {
    asm volatile(
        "mma.sync.aligned.m16n8k16.row.col.f32.f16.f16.f32 "
        "{%0,%1,%2,%3}, {%4,%5,%6,%7}, {%8,%9}, {%0,%1,%2,%3};"
        : "+f"(c[0]), "+f"(c[1]), "+f"(c[2]), "+f"(c[3])
        : "r"(a0), "r"(a1), "r"(a2), "r"(a3), "r"(b0), "r"(b1));
}
__device__ __forceinline__ uint32_t pk(float a, float b) {
    __half2 h = __floats2half2_rn(a, b);
    return *reinterpret_cast<uint32_t*>(&h);
}
__device__ __forceinline__ float silu_f(float x) { return x / (1.0f + __expf(-x)); }

// ---------------- fp32 -> fp16 converter ---------------------------------------
__global__ void cvt_f2h(const float4* __restrict__ src, __half* __restrict__ dst,
                        int n4) {
    int i = blockIdx.x * blockDim.x + threadIdx.x;
    if (i < n4) {
        float4 v = src[i];
        uint2 o;
        o.x = pk(v.x, v.y);
        o.y = pk(v.z, v.w);
        *reinterpret_cast<uint2*>(dst + (size_t)i * 4) = o;
    }
}

// ---------------- shared GEMM machinery (proven R4 core) ------------------------
// CTA tile 128x128, K-chunk 64, 256 threads (8 warps, 2x4 grid of 64x32 warp
// tiles), 2 CTAs/SM, 3-stage cp.async pipeline.
static constexpr int STG_A = 128 * 64 * 2;     // 16KB
static constexpr int STG_B = 64 * 128 * 2;     // 16KB
static constexpr int STG = STG_A + STG_B;      // 32KB
static constexpr int SMEM_DYN = 3 * STG + 128; // ~96KB

// compute(): identical inner loop for both kernels (64x32 warp tiles).
template <typename AccT>
__device__ __forceinline__ void gemm_compute(uint32_t Ab, uint32_t Bb, int lane,
                                             int wm, int wn, AccT& acc) {
    const int sub = lane >> 3, lr = lane & 7;
#pragma unroll
    for (int ks = 0; ks < 4; ++ks) {
        uint32_t bfr[8];
#pragma unroll
        for (int np = 0; np < 2; ++np) {
            int krow = ks * 16 + (sub & 1) * 8 + lr;
            int ng = wn * 4 + np * 2 + (sub >> 1);
            uint32_t addr = Bb + krow * 256 + ((ng ^ (krow & 7)) << 4);
            ldsm4t(bfr[np * 4 + 0], bfr[np * 4 + 1], bfr[np * 4 + 2],
                   bfr[np * 4 + 3], addr);
        }
#pragma unroll
        for (int mb = 0; mb < 4; ++mb) {
            int row = wm * 64 + mb * 16 + (sub & 1) * 8 + lr;
            int q = ks * 2 + (sub >> 1);
            uint32_t addr = Ab + row * 128 + ((q ^ (row & 7)) << 4);
            uint32_t a0, a1, a2, a3;
            ldsm4(a0, a1, a2, a3, addr);
#pragma unroll
            for (int np = 0; np < 2; ++np) {
                mma16816(acc[mb][np * 2 + 0], a0, a1, a2, a3,
                         bfr[np * 4 + 0], bfr[np * 4 + 1]);
                mma16816(acc[mb][np * 2 + 1], a0, a1, a2, a3,
                         bfr[np * 4 + 2], bfr[np * 4 + 3]);
            }
        }
    }
}

__device__ __forceinline__ void cpA_stage(uint32_t sA, const __half* ap, int KDIM,
                                          int tid) {
#pragma unroll
    for (int it = 0; it < 4; ++it) {
        int g = tid + it * 256;
        int r = g >> 3, q = g & 7;                   // 128 rows x 8 chunks
        cp16(sA + r * 128 + ((q ^ (r & 7)) << 4), ap + (size_t)r * KDIM + q * 8);
    }
}

// ---------------- kernel 1: fused gate+up GEMM with SiLU epilogue ----------------
// Combined B tile: 64 K-rows x 128 cols, interleaved 8-col groups
//   [g0][u0][g1][u1]... : even group g -> gate cols, odd -> up cols.
// Each CTA produces a 128 x 64 slab of hid = silu(x@gate) * (x@up).
__global__ void __launch_bounds__(256, 2)
gemm_gateup(const __half* __restrict__ Ag, const __half* __restrict__ Gw,
            const __half* __restrict__ Uw, __half* __restrict__ Hid,
            const int* __restrict__ gs) {
    extern __shared__ char dsm[];
    __shared__ int s_cum[NE];

    const int tid = threadIdx.x;
    if (tid == 0) {
        int c = 0;
#pragma unroll
        for (int k = 0; k < NE; ++k) { s_cum[k] = c; c += gs[k]; }
    }
    __syncthreads();

    const int m0 = blockIdx.y * 128;
    const int n0h = blockIdx.x * 64;                 // 64-col slice of gate AND up
    int e = 0;
#pragma unroll
    for (int k = 1; k < NE; ++k) e += (s_cum[k] <= m0) ? 1 : 0;

    const size_t esz = (size_t)HD * ID;
    const __half* gwp = Gw + e * esz + n0h;
    const __half* uwp = Uw + e * esz + n0h;
    const __half* Ap = Ag + (size_t)m0 * HD;

    const uint32_t base = (smem_u32(dsm) + 127u) & ~127u;
    const int lane = tid & 31, wid = tid >> 5;
    const int wm = wid >> 2, wn = wid & 3;

    auto load_stage = [&](int slot, int ch) {
        const uint32_t sA = base + slot * STG;
        const uint32_t sB = sA + STG_A;
        cpA_stage(sA, Ap + ch * 64, HD, tid);
#pragma unroll
        for (int it = 0; it < 4; ++it) {
            int g = tid + it * 256;
            int r = g >> 4, c = g & 15;              // 64 rows x 16 groups
            const __half* src = (c & 1) ? uwp : gwp;
            cp16(sB + r * 256 + ((c ^ (r & 7)) << 4),
                 src + (size_t)(ch * 64 + r) * ID + (c >> 1) * 8);
        }
        asm volatile("cp.async.commit_group;" ::: "memory");
    };

    float acc[4][4][4];
#pragma unroll
    for (int a = 0; a < 4; ++a)
#pragma unroll
        for (int b = 0; b < 4; ++b)
#pragma unroll
            for (int c = 0; c < 4; ++c) acc[a][b][c] = 0.f;

    constexpr int nch = HD / 64;
    load_stage(0, 0);
    load_stage(1, 1);

#pragma unroll 1
    for (int i = 0; i < nch; ++i) {
        if (i + 1 < nch) asm volatile("cp.async.wait_group 1;" ::: "memory");
        else             asm volatile("cp.async.wait_group 0;" ::: "memory");
        __syncthreads();
        if (i + 2 < nch) load_stage((i + 2) % 3, i + 2);
        const uint32_t Ab = base + (i % 3) * STG;
        gemm_compute(Ab, Ab + STG_A, lane, wm, wn, acc);
    }

    // ---- fused SiLU epilogue: even acc groups = gate, odd = up ----
    const int r0 = m0 + wm * 64 + (lane >> 2);
#pragma unroll
    for (int mb = 0; mb < 4; ++mb) {
#pragma unroll
        for (int np = 0; np < 2; ++np) {
            float* gA = acc[mb][np * 2 + 0];
            float* uA = acc[mb][np * 2 + 1];
            const int rr = r0 + mb * 16;
            const int cc = n0h + (wn * 2 + np) * 8 + (lane & 3) * 2;
            const size_t o0 = (size_t)rr * ID + cc;
            const size_t o1 = (size_t)(rr + 8) * ID + cc;
            *(uint32_t*)(Hid + o0) = pk(silu_f(gA[0]) * uA[0], silu_f(gA[1]) * uA[1]);
            *(uint32_t*)(Hid + o1) = pk(silu_f(gA[2]) * uA[2], silu_f(gA[3]) * uA[3]);
        }
    }
}

// ---------------- kernel 2: down GEMM (fp32 out) --------------------------------
__global__ void __launch_bounds__(256, 2)
gemm_down(const __half* __restrict__ Ag, const __half* __restrict__ Ball,
          float* __restrict__ Cv, const int* __restrict__ gs) {
    extern __shared__ char dsm[];
    __shared__ int s_cum[NE];

    const int tid = threadIdx.x;
    if (tid == 0) {
        int c = 0;
#pragma unroll
        for (int k = 0; k < NE; ++k) { s_cum[k] = c; c += gs[k]; }
    }
    __syncthreads();

    const int m0 = blockIdx.y * 128;
    const int n0 = blockIdx.x * 128;
    int e = 0;
#pragma unroll
    for (int k = 1; k < NE; ++k) e += (s_cum[k] <= m0) ? 1 : 0;

    const __half* Bg = Ball + (size_t)e * ID * HD + n0;
    const __half* Ap = Ag + (size_t)m0 * ID;

    const uint32_t base = (smem_u32(dsm) + 127u) & ~127u;
    const int lane = tid & 31, wid = tid >> 5;
    const int wm = wid >> 2, wn = wid & 3;

    auto load_stage = [&](int slot, int ch) {
        const uint32_t sA = base + slot * STG;
        const uint32_t sB = sA + STG_A;
        cpA_stage(sA, Ap + ch * 64, ID, tid);
        const __half* bp = Bg + (size_t)(ch * 64) * HD;
#pragma unroll
        for (int it = 0; it < 4; ++it) {
            int g = tid + it * 256;
            int r = g >> 4, c = g & 15;              // 64 rows x 16 chunks
            cp16(sB + r * 256 + ((c ^ (r & 7)) << 4),
                 bp + (size_t)r * HD + c * 8);
        }
        asm volatile("cp.async.commit_group;" ::: "memory");
    };

    float acc[4][4][4];
#pragma unroll
    for (int a = 0; a < 4; ++a)
#pragma unroll
        for (int b = 0; b < 4; ++b)
#pragma unroll
            for (int c = 0; c < 4; ++c) acc[a][b][c] = 0.f;

    constexpr int nch = ID / 64;
    load_stage(0, 0);
    load_stage(1, 1);

#pragma unroll 1
    for (int i = 0; i < nch; ++i) {
        if (i + 1 < nch) asm volatile("cp.async.wait_group 1;" ::: "memory");
        else             asm volatile("cp.async.wait_group 0;" ::: "memory");
        __syncthreads();
        if (i + 2 < nch) load_stage((i + 2) % 3, i + 2);
        const uint32_t Ab = base + (i % 3) * STG;
        gemm_compute(Ab, Ab + STG_A, lane, wm, wn, acc);
    }

    const int r0 = m0 + wm * 64 + (lane >> 2);
    const int c0 = n0 + wn * 32 + (lane & 3) * 2;
#pragma unroll
    for (int mb = 0; mb < 4; ++mb) {
#pragma unroll
        for (int nb = 0; nb < 4; ++nb) {
            const int rr = r0 + mb * 16;
            const int cc = c0 + nb * 8;
            float* a = acc[mb][nb];
            *(float2*)(Cv + (size_t)rr * HD + cc)       = make_float2(a[0], a[1]);
            *(float2*)(Cv + (size_t)(rr + 8) * HD + cc) = make_float2(a[2], a[3]);
        }
    }
}

// ---------------- host launcher -------------------------------------------------
extern "C" void kernel_launch(void* const* d_in, const int* in_sizes, int n_in,
                              void* d_out, int out_size) {
    const float* x  = (const float*)d_in[0];
    const float* gw = (const float*)d_in[1];
    const float* uw = (const float*)d_in[2];
    const float* dw = (const float*)d_in[3];
    const int*   gs = (const int*)d_in[4];
    float* out = (float*)d_out;

    // Resolve REAL device addresses of __device__ scratch (host shadow trap).
    void *p_xh = nullptr, *p_hid = nullptr, *p_wh = nullptr;
    cudaGetSymbolAddress(&p_xh, g_xh);
    cudaGetSymbolAddress(&p_hid, g_hid);
    cudaGetSymbolAddress(&p_wh, g_wh);
    __half* xh   = (__half*)p_xh;
    __half* hid  = (__half*)p_hid;
    __half* wh_g = (__half*)p_wh;
    __half* wh_u = wh_g + (size_t)NE * HD * ID;
    __half* wh_d = wh_u + (size_t)NE * HD * ID;

    cudaFuncSetAttribute(gemm_gateup,
                         cudaFuncAttributeMaxDynamicSharedMemorySize, SMEM_DYN);
    cudaFuncSetAttribute(gemm_down,
                         cudaFuncAttributeMaxDynamicSharedMemorySize, SMEM_DYN);

    // fp32 -> fp16 conversions (x and all weights)
    const int nx4 = (TT * HD) / 4;
    cvt_f2h<<<(nx4 + 255) / 256, 256>>>((const float4*)x, xh, nx4);
    const int nw4 = (NE * HD * ID) / 4;
    cvt_f2h<<<(nw4 + 255) / 256, 256>>>((const float4*)gw, wh_g, nw4);
    cvt_f2h<<<(nw4 + 255) / 256, 256>>>((const float4*)uw, wh_u, nw4);
    cvt_f2h<<<(nw4 + 255) / 256, 256>>>((const float4*)dw, wh_d, nw4);

    // hid = silu(x@gate) * (x@up)   (fused, writes hid directly)
    gemm_gateup<<<dim3(ID / 64, TT / 128), 256, SMEM_DYN>>>(xh, wh_g, wh_u, hid, gs);
    // out = hid @ down
    gemm_down<<<dim3(HD / 128, TT / 128), 256, SMEM_DYN>>>(hid, wh_d, out, gs);
}

// round 10
// speedup vs baseline: 1.1222x; 1.1222x over previous
#include <cuda_runtime.h>
#include <cuda_fp16.h>
#include <cstdint>
#include <cstddef>

#define NE 16
#define HD 2048
#define ID 1536
#define TT 32768

// ---------------- device scratch (allocation-free rule) -------------------------
__device__ __half g_xh[(size_t)TT * HD];                  // x fp16          (128MB)
__device__ __half g_gate[(size_t)TT * ID];                // gate proj fp16  ( 96MB)
__device__ __half g_hid[(size_t)TT * ID];                 // silu(g)*up fp16 ( 96MB)
__device__ __half g_wh[(size_t)NE * 3 * HD * ID];         // fp16 weights    (302MB)

// ---------------- helpers -------------------------------------------------------
__device__ __forceinline__ uint32_t smem_u32(const void* p) {
    uint32_t a;
    asm("{ .reg .u64 t; cvta.to.shared.u64 t, %1; cvt.u32.u64 %0, t; }" : "=r"(a) : "l"(p));
    return a;
}
__device__ __forceinline__ void cp16(uint32_t dst, const void* src) {
    asm volatile("cp.async.cg.shared.global [%0], [%1], 16;" :: "r"(dst), "l"(src));
}
__device__ __forceinline__ void ldsm4(uint32_t& r0, uint32_t& r1, uint32_t& r2,
                                      uint32_t& r3, uint32_t a) {
    asm volatile("ldmatrix.sync.aligned.m8n8.x4.shared.b16 {%0,%1,%2,%3}, [%4];"
                 : "=r"(r0), "=r"(r1), "=r"(r2), "=r"(r3) : "r"(a));
}
__device__ __forceinline__ void ldsm4t(uint32_t& r0, uint32_t& r1, uint32_t& r2,
                                       uint32_t& r3, uint32_t a) {
    asm volatile("ldmatrix.sync.aligned.m8n8.x4.trans.shared.b16 {%0,%1,%2,%3}, [%4];"
                 : "=r"(r0), "=r"(r1), "=r"(r2), "=r"(r3) : "r"(a));
}
__device__ __forceinline__ void mma16816(float* c, uint32_t a0, uint32_t a1, uint32_t a2,
                                         uint32_t a3, uint32_t b0, uint32_t b1) {
    asm volatile(
        "mma.sync.aligned.m16n8k16.row.col.f32.f16.f16.f32 "
        "{%0,%1,%2,%3}, {%4,%5,%6,%7}, {%8,%9}, {%0,%1,%2,%3};"
        : "+f"(c[0]), "+f"(c[1]), "+f"(c[2]), "+f"(c[3])
        : "r"(a0), "r"(a1), "r"(a2), "r"(a3), "r"(b0), "r"(b1));
}
__device__ __forceinline__ uint32_t pk(float a, float b) {
    __half2 h = __floats2half2_rn(a, b);
    return *reinterpret_cast<uint32_t*>(&h);
}
__device__ __forceinline__ float silu_f(float x) { return x / (1.0f + __expf(-x)); }

// ---------------- fp32 -> fp16 converter ----------------------------------------
__global__ void cvt_f2h(const float4* __restrict__ src, __half* __restrict__ dst,
                        int n4) {
    int i = blockIdx.x * blockDim.x + threadIdx.x;
    if (i < n4) {
        float4 v = src[i];
        uint2 o;
        o.x = pk(v.x, v.y);
        o.y = pk(v.z, v.w);
        *reinterpret_cast<uint2*>(dst + (size_t)i * 4) = o;
    }
}

// ---------------- grouped GEMM (mma.sync fp16, fp32 accum) ----------------------
// CTA tile 128x256, K-chunk 64, 512 threads (16 warps, 2x8 grid of 64x32 warp
// tiles -> 64 acc regs/thread, no spills), 4-stage cp.async pipeline with
// wait_group 2 (two loads in flight over each barrier).  1 CTA/SM, 192KB smem.
// A fp16 K-major, B fp16 [K,N] N-contiguous.
// MODE 0: write fp16 raw (gate)
// MODE 1: write fp16 silu(G)*acc reading G  (up, fused SiLU)
// MODE 2: write fp32                        (down)
static constexpr int STG_A = 128 * 64 * 2;     // 16KB
static constexpr int STG_B = 64 * 256 * 2;     // 32KB
static constexpr int STG = STG_A + STG_B;      // 48KB
static constexpr int SMEM_DYN = 4 * STG + 128; // ~192KB

template <int KDIM, int NDIM, int MODE>
__global__ void __launch_bounds__(512, 1)
gemm_moe(const __half* __restrict__ Ag, const __half* __restrict__ Ball,
         void* __restrict__ Cv, const __half* __restrict__ Gv,
         const int* __restrict__ gs) {
    extern __shared__ char dsm[];
    __shared__ int s_cum[NE];

    const int tid = threadIdx.x;
    if (tid == 0) {
        int c = 0;
#pragma unroll
        for (int k = 0; k < NE; ++k) { s_cum[k] = c; c += gs[k]; }
    }
    __syncthreads();

    const int m0 = blockIdx.y * 128;
    const int n0 = blockIdx.x * 256;
    int e = 0;
#pragma unroll
    for (int k = 1; k < NE; ++k) e += (s_cum[k] <= m0) ? 1 : 0;

    const __half* Bg = Ball + (size_t)e * KDIM * NDIM + n0;
    const __half* Ap = Ag + (size_t)m0 * KDIM;

    const uint32_t base = (smem_u32(dsm) + 127u) & ~127u;
    const int lane = tid & 31, wid = tid >> 5;
    const int wm = wid >> 3, wn = wid & 7;       // 2x8 warp grid, 64x32 tiles

    // ---- stage loader: A 128x64 (rows 128B), B 64x256 (rows 512B) ----
    auto load_stage = [&](int slot, int ch) {
        const uint32_t sA = base + slot * STG;
        const uint32_t sB = sA + STG_A;
        const __half* ap = Ap + ch * 64;
#pragma unroll
        for (int it = 0; it < 2; ++it) {
            int g = tid + it * 512;
            int r = g >> 3, q = g & 7;               // 128 rows x 8 chunks
            cp16(sA + r * 128 + ((q ^ (r & 7)) << 4),
                 ap + (size_t)r * KDIM + q * 8);
        }
        const __half* bp = Bg + (size_t)(ch * 64) * NDIM;
#pragma unroll
        for (int it = 0; it < 4; ++it) {
            int g = tid + it * 512;
            int r = g >> 5, c = g & 31;              // 64 rows x 32 chunks
            cp16(sB + r * 512 + ((c ^ (r & 7)) << 4),
                 bp + (size_t)r * NDIM + c * 8);
        }
        asm volatile("cp.async.commit_group;" ::: "memory");
    };

    float acc[4][4][4];
#pragma unroll
    for (int a = 0; a < 4; ++a)
#pragma unroll
        for (int b = 0; b < 4; ++b)
#pragma unroll
            for (int c = 0; c < 4; ++c) acc[a][b][c] = 0.f;

    auto compute = [&](int slot) {
        const uint32_t Ab = base + slot * STG;
        const uint32_t Bb = Ab + STG_A;
        const int sub = lane >> 3, lr = lane & 7;
#pragma unroll
        for (int ks = 0; ks < 4; ++ks) {
            uint32_t bfr[8];
#pragma unroll
            for (int np = 0; np < 2; ++np) {
                int krow = ks * 16 + (sub & 1) * 8 + lr;
                int ng = wn * 4 + np * 2 + (sub >> 1);
                uint32_t addr = Bb + krow * 512 + ((ng ^ (krow & 7)) << 4);
                ldsm4t(bfr[np * 4 + 0], bfr[np * 4 + 1], bfr[np * 4 + 2],
                       bfr[np * 4 + 3], addr);
            }
#pragma unroll
            for (int mb = 0; mb < 4; ++mb) {
                int row = wm * 64 + mb * 16 + (sub & 1) * 8 + lr;
                int q = ks * 2 + (sub >> 1);
                uint32_t addr = Ab + row * 128 + ((q ^ (row & 7)) << 4);
                uint32_t a0, a1, a2, a3;
                ldsm4(a0, a1, a2, a3, addr);
#pragma unroll
                for (int np = 0; np < 2; ++np) {
                    mma16816(acc[mb][np * 2 + 0], a0, a1, a2, a3,
                             bfr[np * 4 + 0], bfr[np * 4 + 1]);
                    mma16816(acc[mb][np * 2 + 1], a0, a1, a2, a3,
                             bfr[np * 4 + 2], bfr[np * 4 + 3]);
                }
            }
        }
    };

    const int nch = KDIM / 64;

    // ---- prologue: stages 0,1,2 in flight ----
    load_stage(0, 0);
    load_stage(1, 1);
    load_stage(2, 2);

    // ---- mainloop: 4-slot rotation, wait_group 2 ----
#pragma unroll 1
    for (int i = 0; i < nch; ++i) {
        if (i + 3 <= nch)      asm volatile("cp.async.wait_group 2;" ::: "memory");
        else if (i + 2 == nch) asm volatile("cp.async.wait_group 1;" ::: "memory");
        else                   asm volatile("cp.async.wait_group 0;" ::: "memory");
        __syncthreads();
        if (i + 3 < nch) load_stage((i + 3) & 3, i + 3);
        compute(i & 3);
    }

    // ---- epilogue ----
    const int r0 = m0 + wm * 64 + (lane >> 2);
    const int c0 = n0 + wn * 32 + (lane & 3) * 2;

#pragma unroll
    for (int mb = 0; mb < 4; ++mb) {
#pragma unroll
        for (int nb = 0; nb < 4; ++nb) {
            const int rr = r0 + mb * 16;
            const int cc = c0 + nb * 8;
            const size_t o0 = (size_t)rr * NDIM + cc;
            const size_t o1 = (size_t)(rr + 8) * NDIM + cc;
            float* a = acc[mb][nb];
            if (MODE == 0) {
                __half* C = (__half*)Cv;
                *(uint32_t*)(C + o0) = pk(a[0], a[1]);
                *(uint32_t*)(C + o1) = pk(a[2], a[3]);
            } else if (MODE == 1) {
                __half* C = (__half*)Cv;
                __half2 g0 = *(const __half2*)(Gv + o0);
                __half2 g1 = *(const __half2*)(Gv + o1);
                float2 f0 = __half22float2(g0);
                float2 f1 = __half22float2(g1);
                *(uint32_t*)(C + o0) = pk(silu_f(f0.x) * a[0], silu_f(f0.y) * a[1]);
                *(uint32_t*)(C + o1) = pk(silu_f(f1.x) * a[2], silu_f(f1.y) * a[3]);
            } else {
                float* C = (float*)Cv;
                *(float2*)(C + o0) = make_float2(a[0], a[1]);
                *(float2*)(C + o1) = make_float2(a[2], a[3]);
            }
        }
    }
}

// ---------------- host launcher -------------------------------------------------
extern "C" void kernel_launch(void* const* d_in, const int* in_sizes, int n_in,
                              void* d_out, int out_size) {
    const float* x  = (const float*)d_in[0];
    const float* gw = (const float*)d_in[1];
    const float* uw = (const float*)d_in[2];
    const float* dw = (const float*)d_in[3];
    const int*   gs = (const int*)d_in[4];
    float* out = (float*)d_out;

    // Resolve REAL device addresses of __device__ scratch (host shadow trap).
    void *p_xh = nullptr, *p_gate = nullptr, *p_hid = nullptr, *p_wh = nullptr;
    cudaGetSymbolAddress(&p_xh, g_xh);
    cudaGetSymbolAddress(&p_gate, g_gate);
    cudaGetSymbolAddress(&p_hid, g_hid);
    cudaGetSymbolAddress(&p_wh, g_wh);
    __half* xh   = (__half*)p_xh;
    __half* gate = (__half*)p_gate;
    __half* hid  = (__half*)p_hid;
    __half* wh_g = (__half*)p_wh;
    __half* wh_u = wh_g + (size_t)NE * HD * ID;
    __half* wh_d = wh_u + (size_t)NE * HD * ID;

    cudaFuncSetAttribute(gemm_moe<HD, ID, 0>,
                         cudaFuncAttributeMaxDynamicSharedMemorySize, SMEM_DYN);
    cudaFuncSetAttribute(gemm_moe<HD, ID, 1>,
                         cudaFuncAttributeMaxDynamicSharedMemorySize, SMEM_DYN);
    cudaFuncSetAttribute(gemm_moe<ID, HD, 2>,
                         cudaFuncAttributeMaxDynamicSharedMemorySize, SMEM_DYN);

    // fp32 -> fp16 conversions (x and all weights)
    const int nx4 = (TT * HD) / 4;
    cvt_f2h<<<(nx4 + 255) / 256, 256>>>((const float4*)x, xh, nx4);
    const int nw4 = (NE * HD * ID) / 4;
    cvt_f2h<<<(nw4 + 255) / 256, 256>>>((const float4*)gw, wh_g, nw4);
    cvt_f2h<<<(nw4 + 255) / 256, 256>>>((const float4*)uw, wh_u, nw4);
    cvt_f2h<<<(nw4 + 255) / 256, 256>>>((const float4*)dw, wh_d, nw4);

    // gate = x @ gate_w             -> g_gate (fp16)
    gemm_moe<HD, ID, 0><<<dim3(ID / 256, TT / 128), 512, SMEM_DYN>>>(
        xh, wh_g, gate, nullptr, gs);
    // hid = silu(gate) * (x @ up_w) -> g_hid (fp16, fused epilogue)
    gemm_moe<HD, ID, 1><<<dim3(ID / 256, TT / 128), 512, SMEM_DYN>>>(
        xh, wh_u, hid, gate, gs);
    // out = hid @ down_w            -> out (fp32)
    gemm_moe<ID, HD, 2><<<dim3(HD / 256, TT / 128), 512, SMEM_DYN>>>(
        hid, wh_d, out, nullptr, gs);
}

// round 11
// speedup vs baseline: 1.2194x; 1.0866x over previous
#include <cuda_runtime.h>
#include <cuda_fp16.h>
#include <cstdint>
#include <cstddef>

#define NE 16
#define HD 2048
#define ID 1536
#define TT 32768

// ---------------- device scratch (allocation-free rule) -------------------------
__device__ __half g_xh[(size_t)TT * HD];                  // x fp16          (128MB)
__device__ __half g_hid[(size_t)TT * ID];                 // silu(g)*up fp16 ( 96MB)
__device__ __half g_wh[(size_t)NE * 3 * HD * ID];         // fp16 weights    (302MB)

// ---------------- helpers -------------------------------------------------------
__device__ __forceinline__ uint32_t smem_u32(const void* p) {
    uint32_t a;
    asm("{ .reg .u64 t; cvta.to.shared.u64 t, %1; cvt.u32.u64 %0, t; }" : "=r"(a) : "l"(p));
    return a;
}
__device__ __forceinline__ void cp16(uint32_t dst, const void* src) {
    asm volatile("cp.async.cg.shared.global [%0], [%1], 16;" :: "r"(dst), "l"(src));
}
__device__ __forceinline__ void ldsm4(uint32_t& r0, uint32_t& r1, uint32_t& r2,
                                      uint32_t& r3, uint32_t a) {
    asm volatile("ldmatrix.sync.aligned.m8n8.x4.shared.b16 {%0,%1,%2,%3}, [%4];"
                 : "=r"(r0), "=r"(r1), "=r"(r2), "=r"(r3) : "r"(a));
}
__device__ __forceinline__ void ldsm4t(uint32_t& r0, uint32_t& r1, uint32_t& r2,
                                       uint32_t& r3, uint32_t a) {
    asm volatile("ldmatrix.sync.aligned.m8n8.x4.trans.shared.b16 {%0,%1,%2,%3}, [%4];"
                 : "=r"(r0), "=r"(r1), "=r"(r2), "=r"(r3) : "r"(a));
}
__device__ __forceinline__ void mma16816(float* c, uint32_t a0, uint32_t a1, uint32_t a2,
                                         uint32_t a3, uint32_t b0, uint32_t b1) {
    asm volatile(
        "mma.sync.aligned.m16n8k16.row.col.f32.f16.f16.f32 "
        "{%0,%1,%2,%3}, {%4,%5,%6,%7}, {%8,%9}, {%0,%1,%2,%3};"
        : "+f"(c[0]), "+f"(c[1]), "+f"(c[2]), "+f"(c[3])
        : "r"(a0), "r"(a1), "r"(a2), "r"(a3), "r"(b0), "r"(b1));
}
__device__ __forceinline__ uint32_t pk(float a, float b) {
    __half2 h = __floats2half2_rn(a, b);
    return *reinterpret_cast<uint32_t*>(&h);
}
__device__ __forceinline__ float silu_f(float x) { return x / (1.0f + __expf(-x)); }

// ---------------- fp32 -> fp16 converters ---------------------------------------
__global__ void cvt_f2h(const float4* __restrict__ src, __half* __restrict__ dst,
                        int n4) {
    int i = blockIdx.x * blockDim.x + threadIdx.x;
    if (i < n4) {
        float4 v = src[i];
        uint2 o;
        o.x = pk(v.x, v.y);
        o.y = pk(v.z, v.w);
        *reinterpret_cast<uint2*>(dst + (size_t)i * 4) = o;
    }
}
// all 3 weight matrices in one launch: blockIdx.z selects the matrix
__global__ void cvt_w3(const float4* __restrict__ gw, const float4* __restrict__ uw,
                       const float4* __restrict__ dw, __half* __restrict__ dst,
                       int n4) {
    int i = blockIdx.x * blockDim.x + threadIdx.x;
    if (i >= n4) return;
    const float4* src = (blockIdx.z == 0) ? gw : (blockIdx.z == 1) ? uw : dw;
    float4 v = src[i];
    uint2 o;
    o.x = pk(v.x, v.y);
    o.y = pk(v.z, v.w);
    *reinterpret_cast<uint2*>(dst + (size_t)blockIdx.z * 4 * n4 + (size_t)i * 4) = o;
}

// ---------------- shared GEMM machinery (proven R4 core) ------------------------
// CTA tile 128x128, K-chunk 64, 256 threads (8 warps, 2x4 grid of 64x32 warp
// tiles), 2 CTAs/SM, 3-stage cp.async pipeline.
static constexpr int STG_A = 128 * 64 * 2;     // 16KB
static constexpr int STG_B = 64 * 128 * 2;     // 16KB
static constexpr int STG = STG_A + STG_B;      // 32KB
static constexpr int SMEM_DYN = 3 * STG + 128; // ~96KB

template <typename AccT>
__device__ __forceinline__ void gemm_compute(uint32_t Ab, uint32_t Bb, int lane,
                                             int wm, int wn, AccT& acc) {
    const int sub = lane >> 3, lr = lane & 7;
#pragma unroll
    for (int ks = 0; ks < 4; ++ks) {
        uint32_t bfr[8];
#pragma unroll
        for (int np = 0; np < 2; ++np) {
            int krow = ks * 16 + (sub & 1) * 8 + lr;
            int ng = wn * 4 + np * 2 + (sub >> 1);
            uint32_t addr = Bb + krow * 256 + ((ng ^ (krow & 7)) << 4);
            ldsm4t(bfr[np * 4 + 0], bfr[np * 4 + 1], bfr[np * 4 + 2],
                   bfr[np * 4 + 3], addr);
        }
#pragma unroll
        for (int mb = 0; mb < 4; ++mb) {
            int row = wm * 64 + mb * 16 + (sub & 1) * 8 + lr;
            int q = ks * 2 + (sub >> 1);
            uint32_t addr = Ab + row * 128 + ((q ^ (row & 7)) << 4);
            uint32_t a0, a1, a2, a3;
            ldsm4(a0, a1, a2, a3, addr);
#pragma unroll
            for (int np = 0; np < 2; ++np) {
                mma16816(acc[mb][np * 2 + 0], a0, a1, a2, a3,
                         bfr[np * 4 + 0], bfr[np * 4 + 1]);
                mma16816(acc[mb][np * 2 + 1], a0, a1, a2, a3,
                         bfr[np * 4 + 2], bfr[np * 4 + 3]);
            }
        }
    }
}

__device__ __forceinline__ void cpA_stage(uint32_t sA, const __half* ap, int KDIM,
                                          int tid) {
#pragma unroll
    for (int it = 0; it < 4; ++it) {
        int g = tid + it * 256;
        int r = g >> 3, q = g & 7;                   // 128 rows x 8 chunks
        cp16(sA + r * 128 + ((q ^ (r & 7)) << 4), ap + (size_t)r * KDIM + q * 8);
    }
}

// ---------------- kernel 1: gate+up fused in K (sequential passes) ---------------
// One CTA computes its 128x128 tile TWICE under one continuous pipeline:
// chunks [0,32) with gate weights -> save silu(acc) to 32 fp16x2 regs, zero acc;
// chunks [32,64) with up weights -> epilogue writes silu(g)*u to hid.
// No g_gate tensor, no second launch, no pipeline drain between passes.
__global__ void __launch_bounds__(256, 2)
gemm_gateup(const __half* __restrict__ Ag, const __half* __restrict__ Gw,
            const __half* __restrict__ Uw, __half* __restrict__ Hid,
            const int* __restrict__ gs) {
    extern __shared__ char dsm[];
    __shared__ int s_cum[NE];

    const int tid = threadIdx.x;
    if (tid == 0) {
        int c = 0;
#pragma unroll
        for (int k = 0; k < NE; ++k) { s_cum[k] = c; c += gs[k]; }
    }
    __syncthreads();

    const int m0 = blockIdx.y * 128;
    const int n0 = blockIdx.x * 128;
    int e = 0;
#pragma unroll
    for (int k = 1; k < NE; ++k) e += (s_cum[k] <= m0) ? 1 : 0;

    const size_t esz = (size_t)HD * ID;
    const __half* gwp = Gw + e * esz + n0;
    const __half* uwp = Uw + e * esz + n0;
    const __half* Ap = Ag + (size_t)m0 * HD;

    const uint32_t base = (smem_u32(dsm) + 127u) & ~127u;
    const int lane = tid & 31, wid = tid >> 5;
    const int wm = wid >> 2, wn = wid & 3;

    constexpr int nch = HD / 64;        // 32 chunks per pass
    constexpr int total = 2 * nch;      // 64 chunks total

    auto load_stage = [&](int slot, int c) {
        const uint32_t sA = base + slot * STG;
        const uint32_t sB = sA + STG_A;
        const int kk = (c < nch) ? c : c - nch;
        const __half* bsrc = (c < nch) ? gwp : uwp;
        cpA_stage(sA, Ap + kk * 64, HD, tid);
#pragma unroll
        for (int it = 0; it < 4; ++it) {
            int g = tid + it * 256;
            int r = g >> 4, q = g & 15;              // 64 rows x 16 chunks
            cp16(sB + r * 256 + ((q ^ (r & 7)) << 4),
                 bsrc + (size_t)(kk * 64 + r) * ID + q * 8);
        }
        asm volatile("cp.async.commit_group;" ::: "memory");
    };

    float acc[4][4][4];
#pragma unroll
    for (int a = 0; a < 4; ++a)
#pragma unroll
        for (int b = 0; b < 4; ++b)
#pragma unroll
            for (int c = 0; c < 4; ++c) acc[a][b][c] = 0.f;

    uint32_t gsv[4][4][2];   // saved silu(gate) as fp16x2 pairs (32 regs)

    load_stage(0, 0);
    load_stage(1, 1);

#pragma unroll 1
    for (int i = 0; i < total; ++i) {
        if (i + 1 < total) asm volatile("cp.async.wait_group 1;" ::: "memory");
        else               asm volatile("cp.async.wait_group 0;" ::: "memory");
        __syncthreads();
        if (i + 2 < total) load_stage((i + 2) % 3, i + 2);
        const uint32_t Ab = base + (i % 3) * STG;
        gemm_compute(Ab, Ab + STG_A, lane, wm, wn, acc);

        if (i == nch - 1) {
            // end of gate pass: stash silu(acc), reset acc for up pass.
            // (loads for the up pass are already in flight)
#pragma unroll
            for (int mb = 0; mb < 4; ++mb)
#pragma unroll
                for (int nb = 0; nb < 4; ++nb) {
                    float* a = acc[mb][nb];
                    gsv[mb][nb][0] = pk(silu_f(a[0]), silu_f(a[1]));
                    gsv[mb][nb][1] = pk(silu_f(a[2]), silu_f(a[3]));
                    a[0] = a[1] = a[2] = a[3] = 0.f;
                }
        }
    }

    // ---- epilogue: hid = silu(gate) * up ----
    const int r0 = m0 + wm * 64 + (lane >> 2);
    const int c0 = n0 + wn * 32 + (lane & 3) * 2;
#pragma unroll
    for (int mb = 0; mb < 4; ++mb) {
#pragma unroll
        for (int nb = 0; nb < 4; ++nb) {
            const int rr = r0 + mb * 16;
            const int cc = c0 + nb * 8;
            float* u = acc[mb][nb];
            float2 s0 = __half22float2(*reinterpret_cast<__half2*>(&gsv[mb][nb][0]));
            float2 s1 = __half22float2(*reinterpret_cast<__half2*>(&gsv[mb][nb][1]));
            *(uint32_t*)(Hid + (size_t)rr * ID + cc) = pk(s0.x * u[0], s0.y * u[1]);
            *(uint32_t*)(Hid + (size_t)(rr + 8) * ID + cc) = pk(s1.x * u[2], s1.y * u[3]);
        }
    }
}

// ---------------- kernel 2: down GEMM (fp32 out) --------------------------------
__global__ void __launch_bounds__(256, 2)
gemm_down(const __half* __restrict__ Ag, const __half* __restrict__ Ball,
          float* __restrict__ Cv, const int* __restrict__ gs) {
    extern __shared__ char dsm[];
    __shared__ int s_cum[NE];

    const int tid = threadIdx.x;
    if (tid == 0) {
        int c = 0;
#pragma unroll
        for (int k = 0; k < NE; ++k) { s_cum[k] = c; c += gs[k]; }
    }
    __syncthreads();

    const int m0 = blockIdx.y * 128;
    const int n0 = blockIdx.x * 128;
    int e = 0;
#pragma unroll
    for (int k = 1; k < NE; ++k) e += (s_cum[k] <= m0) ? 1 : 0;

    const __half* Bg = Ball + (size_t)e * ID * HD + n0;
    const __half* Ap = Ag + (size_t)m0 * ID;

    const uint32_t base = (smem_u32(dsm) + 127u) & ~127u;
    const int lane = tid & 31, wid = tid >> 5;
    const int wm = wid >> 2, wn = wid & 3;

    auto load_stage = [&](int slot, int ch) {
        const uint32_t sA = base + slot * STG;
        const uint32_t sB = sA + STG_A;
        cpA_stage(sA, Ap + ch * 64, ID, tid);
        const __half* bp = Bg + (size_t)(ch * 64) * HD;
#pragma unroll
        for (int it = 0; it < 4; ++it) {
            int g = tid + it * 256;
            int r = g >> 4, c = g & 15;              // 64 rows x 16 chunks
            cp16(sB + r * 256 + ((c ^ (r & 7)) << 4),
                 bp + (size_t)r * HD + c * 8);
        }
        asm volatile("cp.async.commit_group;" ::: "memory");
    };

    float acc[4][4][4];
#pragma unroll
    for (int a = 0; a < 4; ++a)
#pragma unroll
        for (int b = 0; b < 4; ++b)
#pragma unroll
            for (int c = 0; c < 4; ++c) acc[a][b][c] = 0.f;

    constexpr int nch = ID / 64;
    load_stage(0, 0);
    load_stage(1, 1);

#pragma unroll 1
    for (int i = 0; i < nch; ++i) {
        if (i + 1 < nch) asm volatile("cp.async.wait_group 1;" ::: "memory");
        else             asm volatile("cp.async.wait_group 0;" ::: "memory");
        __syncthreads();
        if (i + 2 < nch) load_stage((i + 2) % 3, i + 2);
        const uint32_t Ab = base + (i % 3) * STG;
        gemm_compute(Ab, Ab + STG_A, lane, wm, wn, acc);
    }

    const int r0 = m0 + wm * 64 + (lane >> 2);
    const int c0 = n0 + wn * 32 + (lane & 3) * 2;
#pragma unroll
    for (int mb = 0; mb < 4; ++mb) {
#pragma unroll
        for (int nb = 0; nb < 4; ++nb) {
            const int rr = r0 + mb * 16;
            const int cc = c0 + nb * 8;
            float* a = acc[mb][nb];
            *(float2*)(Cv + (size_t)rr * HD + cc)       = make_float2(a[0], a[1]);
            *(float2*)(Cv + (size_t)(rr + 8) * HD + cc) = make_float2(a[2], a[3]);
        }
    }
}

// ---------------- host launcher -------------------------------------------------
extern "C" void kernel_launch(void* const* d_in, const int* in_sizes, int n_in,
                              void* d_out, int out_size) {
    const float* x  = (const float*)d_in[0];
    const float* gw = (const float*)d_in[1];
    const float* uw = (const float*)d_in[2];
    const float* dw = (const float*)d_in[3];
    const int*   gs = (const int*)d_in[4];
    float* out = (float*)d_out;

    // Resolve REAL device addresses of __device__ scratch (host shadow trap).
    void *p_xh = nullptr, *p_hid = nullptr, *p_wh = nullptr;
    cudaGetSymbolAddress(&p_xh, g_xh);
    cudaGetSymbolAddress(&p_hid, g_hid);
    cudaGetSymbolAddress(&p_wh, g_wh);
    __half* xh   = (__half*)p_xh;
    __half* hid  = (__half*)p_hid;
    __half* wh_g = (__half*)p_wh;
    __half* wh_u = wh_g + (size_t)NE * HD * ID;
    __half* wh_d = wh_u + (size_t)NE * HD * ID;

    cudaFuncSetAttribute(gemm_gateup,
                         cudaFuncAttributeMaxDynamicSharedMemorySize, SMEM_DYN);
    cudaFuncSetAttribute(gemm_down,
                         cudaFuncAttributeMaxDynamicSharedMemorySize, SMEM_DYN);

    // fp32 -> fp16 conversions
    const int nx4 = (TT * HD) / 4;
    cvt_f2h<<<(nx4 + 255) / 256, 256>>>((const float4*)x, xh, nx4);
    const int nw4 = (NE * HD * ID) / 4;
    cvt_w3<<<dim3((nw4 + 255) / 256, 1, 3), 256>>>(
        (const float4*)gw, (const float4*)uw, (const float4*)dw, wh_g, nw4);

    // hid = silu(x@gate) * (x@up)    (K-sequential fusion, one launch)
    gemm_gateup<<<dim3(ID / 128, TT / 128), 256, SMEM_DYN>>>(xh, wh_g, wh_u, hid, gs);
    // out = hid @ down
    gemm_down<<<dim3(HD / 128, TT / 128), 256, SMEM_DYN>>>(hid, wh_d, out, gs);
}

// round 12
// speedup vs baseline: 1.2771x; 1.0474x over previous
#include <cuda_runtime.h>
#include <cuda_fp16.h>
#include <cstdint>
#include <cstddef>

#define NE 16
#define HD 2048
#define ID 1536
#define TT 32768

// ---------------- device scratch (allocation-free rule) -------------------------
__device__ __half g_xh[(size_t)TT * HD];                  // x fp16          (128MB)
__device__ __half g_gate[(size_t)TT * ID];                // gate proj fp16  ( 96MB)
__device__ __half g_hid[(size_t)TT * ID];                 // silu(g)*up fp16 ( 96MB)
__device__ __half g_wh[(size_t)NE * 3 * HD * ID];         // fp16 weights    (302MB)

// ---------------- helpers -------------------------------------------------------
__device__ __forceinline__ uint32_t smem_u32(const void* p) {
    uint32_t a;
    asm("{ .reg .u64 t; cvta.to.shared.u64 t, %1; cvt.u32.u64 %0, t; }" : "=r"(a) : "l"(p));
    return a;
}
__device__ __forceinline__ void cp16(uint32_t dst, const void* src) {
    asm volatile("cp.async.cg.shared.global [%0], [%1], 16;" :: "r"(dst), "l"(src));
}
__device__ __forceinline__ void ldsm4(uint32_t& r0, uint32_t& r1, uint32_t& r2,
                                      uint32_t& r3, uint32_t a) {
    asm volatile("ldmatrix.sync.aligned.m8n8.x4.shared.b16 {%0,%1,%2,%3}, [%4];"
                 : "=r"(r0), "=r"(r1), "=r"(r2), "=r"(r3) : "r"(a));
}
__device__ __forceinline__ void ldsm4t(uint32_t& r0, uint32_t& r1, uint32_t& r2,
                                       uint32_t& r3, uint32_t a) {
    asm volatile("ldmatrix.sync.aligned.m8n8.x4.trans.shared.b16 {%0,%1,%2,%3}, [%4];"
                 : "=r"(r0), "=r"(r1), "=r"(r2), "=r"(r3) : "r"(a));
}
__device__ __forceinline__ void mma16816(float* c, uint32_t a0, uint32_t a1, uint32_t a2,
                                         uint32_t a3, uint32_t b0, uint32_t b1) {
    asm volatile(
        "mma.sync.aligned.m16n8k16.row.col.f32.f16.f16.f32 "
        "{%0,%1,%2,%3}, {%4,%5,%6,%7}, {%8,%9}, {%0,%1,%2,%3};"
        : "+f"(c[0]), "+f"(c[1]), "+f"(c[2]), "+f"(c[3])
        : "r"(a0), "r"(a1), "r"(a2), "r"(a3), "r"(b0), "r"(b1));
}
__device__ __forceinline__ uint32_t pk(float a, float b) {
    __half2 h = __floats2half2_rn(a, b);
    return *reinterpret_cast<uint32_t*>(&h);
}
__device__ __forceinline__ float silu_f(float x) { return x / (1.0f + __expf(-x)); }

// ---------------- fp32 -> fp16 converters ---------------------------------------
__global__ void cvt_f2h(const float4* __restrict__ src, __half* __restrict__ dst,
                        int n4) {
    int i = blockIdx.x * blockDim.x + threadIdx.x;
    if (i < n4) {
        float4 v = src[i];
        uint2 o;
        o.x = pk(v.x, v.y);
        o.y = pk(v.z, v.w);
        *reinterpret_cast<uint2*>(dst + (size_t)i * 4) = o;
    }
}
__global__ void cvt_w3(const float4* __restrict__ gw, const float4* __restrict__ uw,
                       const float4* __restrict__ dw, __half* __restrict__ dst,
                       int n4) {
    int i = blockIdx.x * blockDim.x + threadIdx.x;
    if (i >= n4) return;
    const float4* src = (blockIdx.z == 0) ? gw : (blockIdx.z == 1) ? uw : dw;
    float4 v = src[i];
    uint2 o;
    o.x = pk(v.x, v.y);
    o.y = pk(v.z, v.w);
    *reinterpret_cast<uint2*>(dst + (size_t)blockIdx.z * 4 * n4 + (size_t)i * 4) = o;
}

// ---------------- grouped GEMM (mma.sync fp16, fp32 accum) ----------------------
// R4 core: CTA tile 128x128, K-chunk 64, 256 threads (8 warps, 2x4 grid of 64x32
// warp tiles), 2 CTAs/SM, 3-stage cp.async pipeline.
// NEW: the 8 per-thread cp.async issues for chunk i+2 are INTERLEAVED into the
// 4 ks-steps of compute(i) (volatile-asm order = issue order), so the tensor
// pipe no longer idles through a load burst at each chunk top.
// MODE 0: write fp16 raw (gate)
// MODE 1: write fp16 silu(G)*acc reading G  (up, fused SiLU)
// MODE 2: write fp32                        (down)
static constexpr int STG_A = 128 * 64 * 2;     // 16KB
static constexpr int STG_B = 64 * 128 * 2;     // 16KB
static constexpr int STG = STG_A + STG_B;      // 32KB
static constexpr int SMEM_DYN = 3 * STG + 128; // ~96KB

template <int KDIM, int NDIM, int MODE>
__global__ void __launch_bounds__(256, 2)
gemm_moe(const __half* __restrict__ Ag, const __half* __restrict__ Ball,
         void* __restrict__ Cv, const __half* __restrict__ Gv,
         const int* __restrict__ gs) {
    extern __shared__ char dsm[];
    __shared__ int s_cum[NE];

    const int tid = threadIdx.x;
    if (tid == 0) {
        int c = 0;
#pragma unroll
        for (int k = 0; k < NE; ++k) { s_cum[k] = c; c += gs[k]; }
    }
    __syncthreads();

    const int m0 = blockIdx.y * 128;
    const int n0 = blockIdx.x * 128;
    int e = 0;
#pragma unroll
    for (int k = 1; k < NE; ++k) e += (s_cum[k] <= m0) ? 1 : 0;

    const __half* Bg = Ball + (size_t)e * KDIM * NDIM + n0;
    const __half* Ap = Ag + (size_t)m0 * KDIM;

    const uint32_t base = (smem_u32(dsm) + 127u) & ~127u;
    const int lane = tid & 31, wid = tid >> 5;
    const int wm = wid >> 2, wn = wid & 3;

    // ---- per-thread load geometry (constant for whole kernel) ----
    // A: thread covers rows rA+32*it (it=0..3), 16B chunk qA. Swizzle uses
    // row&7 which is invariant to +32 -> smem offset stride = it*4096.
    const int rA = tid >> 3, qA = tid & 7;
    const uint32_t oA0 = rA * 128 + ((qA ^ (rA & 7)) << 4);
    const __half* gAp = Ap + (size_t)rA * KDIM + qA * 8;
    // B: rows rB+16*it, chunk cB; row&7 invariant to +16 -> stride it*4096.
    const int rB = tid >> 4, cB = tid & 15;
    const uint32_t oB0 = rB * 256 + ((cB ^ (rB & 7)) << 4);
    const __half* gBp = Bg + (size_t)rB * NDIM + cB * 8;

    auto load_full = [&](int slot, int ch) {   // prologue bulk loader
        const uint32_t dA = base + slot * STG + oA0;
        const uint32_t dB = base + slot * STG + STG_A + oB0;
        const __half* sa = gAp + ch * 64;
        const __half* sb = gBp + (size_t)(ch * 64) * NDIM;
#pragma unroll
        for (int it = 0; it < 4; ++it)
            cp16(dA + it * 4096, sa + (size_t)(it * 32) * KDIM);
#pragma unroll
        for (int it = 0; it < 4; ++it)
            cp16(dB + it * 4096, sb + (size_t)(it * 16) * NDIM);
        asm volatile("cp.async.commit_group;" ::: "memory");
    };

    float acc[4][4][4];
#pragma unroll
    for (int a = 0; a < 4; ++a)
#pragma unroll
        for (int b = 0; b < 4; ++b)
#pragma unroll
            for (int c = 0; c < 4; ++c) acc[a][b][c] = 0.f;

    // compute chunk in slot, interleaving loads for chunk 'ch' into slot 'dst'
    auto step = [&](int slot, int dst, int ch, bool doload) {
        const uint32_t Ab = base + slot * STG;
        const uint32_t Bb = Ab + STG_A;
        const uint32_t dA = base + dst * STG + oA0;
        const uint32_t dB = base + dst * STG + STG_A + oB0;
        const __half* sa = gAp + ch * 64;
        const __half* sb = gBp + (size_t)(ch * 64) * NDIM;
        const int sub = lane >> 3, lr = lane & 7;
#pragma unroll
        for (int ks = 0; ks < 4; ++ks) {
            uint32_t bfr[8];
#pragma unroll
            for (int np = 0; np < 2; ++np) {
                int krow = ks * 16 + (sub & 1) * 8 + lr;
                int ng = wn * 4 + np * 2 + (sub >> 1);
                uint32_t addr = Bb + krow * 256 + ((ng ^ (krow & 7)) << 4);
                ldsm4t(bfr[np * 4 + 0], bfr[np * 4 + 1], bfr[np * 4 + 2],
                       bfr[np * 4 + 3], addr);
            }
            if (doload) {   // 1 A-load + 1 B-load per ks step (8 total / thread)
                cp16(dA + ks * 4096, sa + (size_t)(ks * 32) * KDIM);
                cp16(dB + ks * 4096, sb + (size_t)(ks * 16) * NDIM);
            }
#pragma unroll
            for (int mb = 0; mb < 4; ++mb) {
                int row = wm * 64 + mb * 16 + (sub & 1) * 8 + lr;
                int q = ks * 2 + (sub >> 1);
                uint32_t addr = Ab + row * 128 + ((q ^ (row & 7)) << 4);
                uint32_t a0, a1, a2, a3;
                ldsm4(a0, a1, a2, a3, addr);
#pragma unroll
                for (int np = 0; np < 2; ++np) {
                    mma16816(acc[mb][np * 2 + 0], a0, a1, a2, a3,
                             bfr[np * 4 + 0], bfr[np * 4 + 1]);
                    mma16816(acc[mb][np * 2 + 1], a0, a1, a2, a3,
                             bfr[np * 4 + 2], bfr[np * 4 + 3]);
                }
            }
        }
        if (doload) asm volatile("cp.async.commit_group;" ::: "memory");
    };

    const int nch = KDIM / 64;

    load_full(0, 0);
    load_full(1, 1);

#pragma unroll 1
    for (int i = 0; i < nch; ++i) {
        if (i + 1 < nch) asm volatile("cp.async.wait_group 1;" ::: "memory");
        else             asm volatile("cp.async.wait_group 0;" ::: "memory");
        __syncthreads();
        const bool dl = (i + 2 < nch);
        step(i % 3, (i + 2) % 3, dl ? (i + 2) : 0, dl);
    }

    // ---- epilogue ----
    const int r0 = m0 + wm * 64 + (lane >> 2);
    const int c0 = n0 + wn * 32 + (lane & 3) * 2;

#pragma unroll
    for (int mb = 0; mb < 4; ++mb) {
#pragma unroll
        for (int nb = 0; nb < 4; ++nb) {
            const int rr = r0 + mb * 16;
            const int cc = c0 + nb * 8;
            const size_t o0 = (size_t)rr * NDIM + cc;
            const size_t o1 = (size_t)(rr + 8) * NDIM + cc;
            float* a = acc[mb][nb];
            if (MODE == 0) {
                __half* C = (__half*)Cv;
                *(uint32_t*)(C + o0) = pk(a[0], a[1]);
                *(uint32_t*)(C + o1) = pk(a[2], a[3]);
            } else if (MODE == 1) {
                __half* C = (__half*)Cv;
                __half2 g0 = *(const __half2*)(Gv + o0);
                __half2 g1 = *(const __half2*)(Gv + o1);
                float2 f0 = __half22float2(g0);
                float2 f1 = __half22float2(g1);
                *(uint32_t*)(C + o0) = pk(silu_f(f0.x) * a[0], silu_f(f0.y) * a[1]);
                *(uint32_t*)(C + o1) = pk(silu_f(f1.x) * a[2], silu_f(f1.y) * a[3]);
            } else {
                float* C = (float*)Cv;
                *(float2*)(C + o0) = make_float2(a[0], a[1]);
                *(float2*)(C + o1) = make_float2(a[2], a[3]);
            }
        }
    }
}

// ---------------- host launcher -------------------------------------------------
extern "C" void kernel_launch(void* const* d_in, const int* in_sizes, int n_in,
                              void* d_out, int out_size) {
    const float* x  = (const float*)d_in[0];
    const float* gw = (const float*)d_in[1];
    const float* uw = (const float*)d_in[2];
    const float* dw = (const float*)d_in[3];
    const int*   gs = (const int*)d_in[4];
    float* out = (float*)d_out;

    // Resolve REAL device addresses of __device__ scratch (host shadow trap).
    void *p_xh = nullptr, *p_gate = nullptr, *p_hid = nullptr, *p_wh = nullptr;
    cudaGetSymbolAddress(&p_xh, g_xh);
    cudaGetSymbolAddress(&p_gate, g_gate);
    cudaGetSymbolAddress(&p_hid, g_hid);
    cudaGetSymbolAddress(&p_wh, g_wh);
    __half* xh   = (__half*)p_xh;
    __half* gate = (__half*)p_gate;
    __half* hid  = (__half*)p_hid;
    __half* wh_g = (__half*)p_wh;
    __half* wh_u = wh_g + (size_t)NE * HD * ID;
    __half* wh_d = wh_u + (size_t)NE * HD * ID;

    cudaFuncSetAttribute(gemm_moe<HD, ID, 0>,
                         cudaFuncAttributeMaxDynamicSharedMemorySize, SMEM_DYN);
    cudaFuncSetAttribute(gemm_moe<HD, ID, 1>,
                         cudaFuncAttributeMaxDynamicSharedMemorySize, SMEM_DYN);
    cudaFuncSetAttribute(gemm_moe<ID, HD, 2>,
                         cudaFuncAttributeMaxDynamicSharedMemorySize, SMEM_DYN);

    // fp32 -> fp16 conversions
    const int nx4 = (TT * HD) / 4;
    cvt_f2h<<<(nx4 + 255) / 256, 256>>>((const float4*)x, xh, nx4);
    const int nw4 = (NE * HD * ID) / 4;
    cvt_w3<<<dim3((nw4 + 255) / 256, 1, 3), 256>>>(
        (const float4*)gw, (const float4*)uw, (const float4*)dw, wh_g, nw4);

    // gate = x @ gate_w             -> g_gate (fp16)
    gemm_moe<HD, ID, 0><<<dim3(ID / 128, TT / 128), 256, SMEM_DYN>>>(
        xh, wh_g, gate, nullptr, gs);
    // hid = silu(gate) * (x @ up_w) -> g_hid (fp16, fused epilogue)
    gemm_moe<HD, ID, 1><<<dim3(ID / 128, TT / 128), 256, SMEM_DYN>>>(
        xh, wh_u, hid, gate, gs);
    // out = hid @ down_w            -> out (fp32)
    gemm_moe<ID, HD, 2><<<dim3(HD / 128, TT / 128), 256, SMEM_DYN>>>(
        hid, wh_d, out, nullptr, gs);
}